// round 11
// baseline (speedup 1.0000x reference)
#include <cuda_runtime.h>
#include <math.h>
#include <stdint.h>

#define NHYP 64
#define D 320
#define NH 4
#define HD 80
#define HALF 40
#define TK 256
#define TCACHE 255
#define FF 2048
#define NL 5

// ---------------- scratch (device globals) ----------------
__device__ float g_tgt[NHYP * D];
__device__ float g_kself[NL * NHYP * TK * D];
__device__ float g_kcross[NL * NHYP * TK * D];
__device__ float g_ff[NHYP * FF];
__device__ float g_mu[NL * NHYP * TCACHE];
__device__ float g_rs[NL * NHYP * TCACHE];
__device__ float g_rotc[TK * HALF];
__device__ float g_rots[TK * HALF];
__device__ float g_qc[HALF];
__device__ float g_qs[HALF];

// ---------------- helpers ----------------
__device__ __forceinline__ uint32_t f2tf(float f) {
    uint32_t u;
    asm("cvt.rna.tf32.f32 %0, %1;" : "=r"(u) : "f"(f));
    return u;
}
__device__ __forceinline__ void mma_tf32(float* d, uint32_t a0, uint32_t a1,
                                         uint32_t a2, uint32_t a3, uint32_t b0,
                                         uint32_t b1) {
    asm volatile(
        "mma.sync.aligned.m16n8k8.row.col.f32.tf32.tf32.f32 "
        "{%0,%1,%2,%3}, {%4,%5,%6,%7}, {%8,%9}, {%0,%1,%2,%3};"
        : "+f"(d[0]), "+f"(d[1]), "+f"(d[2]), "+f"(d[3])
        : "r"(a0), "r"(a1), "r"(a2), "r"(a3), "r"(b0), "r"(b1));
}

// ---------------- xPos tables ----------------
__global__ void k_tables(const int* __restrict__ qoff) {
    int e = blockIdx.x * blockDim.x + threadIdx.x;
    if (e < TK * HALF) {
        int t = e / HALF, i = e % HALF;
        float bs = (2.0f * i + 0.4f * HD) / (1.4f * HD);
        float invf = powf(10000.0f, -(float)i / HALF);
        float power = ((float)t - 128.0f) / 320.0f;
        float z = powf(bs, -power);
        float th = (float)t * invf;
        g_rotc[e] = cosf(th) * z;
        g_rots[e] = sinf(th) * z;
    } else if (e < TK * HALF + HALF) {
        int i = e - TK * HALF;
        int off = qoff[0];
        int total = off + 1;
        int minp = -((total + 1) >> 1);
        float bs = (2.0f * i + 0.4f * HD) / (1.4f * HD);
        float invf = powf(10000.0f, -(float)i / HALF);
        float pq = (float)(minp + total - 1) / 320.0f;
        float z = powf(bs, pq);
        float th = (float)(total - 1) * invf;
        g_qc[i] = cosf(th) * z;
        g_qs[i] = sinf(th) * z;
    }
}

__global__ void k_embed(const int* __restrict__ toks, const float* __restrict__ table) {
    int h = blockIdx.x, d = threadIdx.x;
    g_tgt[h * D + d] = table[(long)toks[h] * D + d];
}

__global__ void k_rowstats(const float* __restrict__ cached) {
    int row = blockIdx.x * 8 + (threadIdx.x >> 5);
    if (row >= NL * NHYP * TCACHE) return;
    int lane = threadIdx.x & 31;
    const float* p = cached + (long)row * D;
    float s = 0.f, s2 = 0.f;
    for (int j = lane; j < D; j += 32) {
        float v = p[j];
        s += v;
        s2 += v * v;
    }
#pragma unroll
    for (int o = 16; o; o >>= 1) {
        s += __shfl_xor_sync(0xffffffffu, s, o);
        s2 += __shfl_xor_sync(0xffffffffu, s2, o);
    }
    if (lane == 0) {
        float mu = s * (1.0f / D);
        float var = s2 * (1.0f / D) - mu * mu;
        g_mu[row] = mu;
        g_rs[row] = rsqrtf(var + 1e-5f);
    }
}

// ---------------- batched K-projection GEMM (all 10, R7 inner layout) ----------------
#define GBM 128
#define GBN 64
#define ASTRIDE 40
__global__ void __launch_bounds__(256) k_gemm_all(
    const float* __restrict__ cached, const float* __restrict__ memory,
    const float* __restrict__ ln_w, const float* __restrict__ ln_b,
    const float* __restrict__ sa_w, const float* __restrict__ sa_b,
    const float* __restrict__ ca_w, const float* __restrict__ ca_b) {
    __shared__ uint32_t As[GBM][ASTRIDE];   // raw f32 bits (MMA truncates A)
    __shared__ uint32_t Bs[32][GBN + 8];    // rna tf32, k-major
    __shared__ float sw[D], sb[D];
    int z = blockIdx.z;
    bool selfmode = (z < 5);
    int l = selfmode ? z : z - 5;
    const float* Araw = selfmode ? cached + (long)l * NHYP * TCACHE * D : memory;
    const float* B = (selfmode ? sa_w : ca_w) + (long)l * 4 * D * D + D * D;
    const float* bias = (selfmode ? sa_b : ca_b) + l * 4 * D + D;
    float* out = (selfmode ? g_kself : g_kcross) + (long)l * NHYP * TK * D;
    int loff = l * NHYP * TCACHE;
    int tid = threadIdx.x;
    if (selfmode) {
        const float* lw = ln_w + l * 3 * D;
        const float* lb = ln_b + l * 3 * D;
        for (int i = tid; i < D; i += 256) {
            sw[i] = lw[i];
            sb[i] = lb[i];
        }
    }
    __syncthreads();
    int m0 = blockIdx.x * GBM, n0 = blockIdx.y * GBN;
    int warp = tid >> 5, lane = tid & 31;
    int wm = warp >> 1, wn = warp & 1;
    int g = lane >> 2, c = lane & 3;
    float acc[2][4][4];
#pragma unroll
    for (int a = 0; a < 2; a++)
#pragma unroll
        for (int bb = 0; bb < 4; bb++)
#pragma unroll
            for (int cc = 0; cc < 4; cc++) acc[a][bb][cc] = 0.f;

    for (int k0 = 0; k0 < D; k0 += 32) {
#pragma unroll
        for (int i = 0; i < 4; i++) {
            int idx = tid + 256 * i;
            int row = idx >> 3, c4 = (idx & 7) * 4;
            int m = m0 + row;
            float4 v = make_float4(0.f, 0.f, 0.f, 0.f);
            if (selfmode) {
                int hyp = m >> 8, t = m & 255;
                if (t < TCACHE) {
                    int r = hyp * TCACHE + t;
                    v = *(const float4*)&Araw[(long)r * D + k0 + c4];
                    float m_ = g_mu[loff + r], rr = g_rs[loff + r];
                    v.x = (v.x - m_) * rr * sw[k0 + c4 + 0] + sb[k0 + c4 + 0];
                    v.y = (v.y - m_) * rr * sw[k0 + c4 + 1] + sb[k0 + c4 + 1];
                    v.z = (v.z - m_) * rr * sw[k0 + c4 + 2] + sb[k0 + c4 + 2];
                    v.w = (v.w - m_) * rr * sw[k0 + c4 + 3] + sb[k0 + c4 + 3];
                }
            } else {
                v = *(const float4*)&Araw[(long)m * D + k0 + c4];
            }
            int base = (c4 & ~7) + ((c4 & 4) ? 1 : 0);
            As[row][base + 0] = __float_as_uint(v.x);
            As[row][base + 2] = __float_as_uint(v.y);
            As[row][base + 4] = __float_as_uint(v.z);
            As[row][base + 6] = __float_as_uint(v.w);
        }
#pragma unroll
        for (int i = 0; i < 2; i++) {
            int idx = tid + 256 * i;
            int k = idx >> 4, n4 = (idx & 15) * 4;
            float4 v = *(const float4*)&B[(long)(k0 + k) * D + n0 + n4];
            Bs[k][n4 + 0] = f2tf(v.x);
            Bs[k][n4 + 1] = f2tf(v.y);
            Bs[k][n4 + 2] = f2tf(v.z);
            Bs[k][n4 + 3] = f2tf(v.w);
        }
        __syncthreads();
#pragma unroll
        for (int ks = 0; ks < 4; ks++) {
            int kc = ks * 8 + 2 * c;
            uint2 a0[2], a1[2];
            uint32_t bfr[4][2];
#pragma unroll
            for (int mi = 0; mi < 2; mi++) {
                int r = wm * 32 + mi * 16 + g;
                a0[mi] = *(const uint2*)&As[r][kc];
                a1[mi] = *(const uint2*)&As[r + 8][kc];
            }
#pragma unroll
            for (int ni = 0; ni < 4; ni++) {
                int nn = wn * 32 + ni * 8;
                bfr[ni][0] = Bs[ks * 8 + c][nn + g];
                bfr[ni][1] = Bs[ks * 8 + c + 4][nn + g];
            }
#pragma unroll
            for (int mi = 0; mi < 2; mi++)
#pragma unroll
                for (int ni = 0; ni < 4; ni++)
                    mma_tf32(acc[mi][ni], a0[mi].x, a1[mi].x, a0[mi].y, a1[mi].y,
                             bfr[ni][0], bfr[ni][1]);
        }
        __syncthreads();
    }
#pragma unroll
    for (int mi = 0; mi < 2; mi++) {
        int r0 = m0 + wm * 32 + mi * 16 + g;
        int r1 = r0 + 8;
        int t0 = r0 & 255, t1 = r1 & 255;
#pragma unroll
        for (int ni = 0; ni < 4; ni++) {
            int nn = n0 + wn * 32 + ni * 8 + 2 * c;
            int p = (nn % HD) >> 1;
            float be = bias[nn], bo = bias[nn + 1];
            {
                float cc = g_rotc[t0 * HALF + p], ss = g_rots[t0 * HALF + p];
                float e = acc[mi][ni][0] + be, o = acc[mi][ni][1] + bo;
                *(float2*)&out[(long)r0 * D + nn] =
                    make_float2(e * cc - o * ss, o * cc + e * ss);
            }
            {
                float cc = g_rotc[t1 * HALF + p], ss = g_rots[t1 * HALF + p];
                float e = acc[mi][ni][2] + be, o = acc[mi][ni][3] + bo;
                *(float2*)&out[(long)r1 * D + nn] =
                    make_float2(e * cc - o * ss, o * cc + e * ss);
            }
        }
    }
}

// ---------------- FULLY fused attention: LN + qproj(+k255proj) + scores + softmax
//                  + LN-folded p@X + Wv + Wo + residual.  grid 64, block (320,2) ----
__global__ void k_attn_full(const float* __restrict__ X, int selfmode, int loff, int l,
                            const float* __restrict__ lnw, const float* __restrict__ lnb,
                            const unsigned char* __restrict__ mask,
                            const float* __restrict__ Wq, const float* __restrict__ bq,
                            const float* __restrict__ Wk, const float* __restrict__ bk,
                            const float* __restrict__ Wv, const float* __restrict__ bv,
                            const float* __restrict__ Wo, const float* __restrict__ bo) {
    __shared__ float xs[D];        // LN'd tgt (stays live: nv for y-combine)
    __shared__ float qs[D];        // rotated scaled q; later reused as z
    __shared__ float k255[D];      // rotated k row 255 (self only)
    __shared__ float col[2][D];    // matvec staging
    __shared__ float p[NH][TK];
    __shared__ float ys[NH][D];
    __shared__ float py[2][NH][D];
    __shared__ float part[2][D];
    __shared__ float red[20];
    __shared__ float redv[2][8];
    __shared__ float val[2];
    __shared__ float redc[4][4];
    __shared__ float corr[NH];
    __shared__ float mv[2];
    int h = blockIdx.x, tx = threadIdx.x, ty = threadIdx.y;
    int ft = ty * 320 + tx;
    int warp = ft >> 5, lane = ft & 31;
    // ---- phase 0: LN of tgt[h] ----
    float v = (ft < D) ? g_tgt[h * D + ft] : 0.f;
    float s = v;
#pragma unroll
    for (int o = 16; o; o >>= 1) s += __shfl_xor_sync(0xffffffffu, s, o);
    if (lane == 0) red[warp] = s;
    __syncthreads();
    if (ft == 0) {
        float a = 0.f;
        for (int i = 0; i < 20; i++) a += red[i];
        mv[0] = a * (1.0f / D);
    }
    __syncthreads();
    float dv = v - mv[0];
    float q2 = (ft < D) ? dv * dv : 0.f;
#pragma unroll
    for (int o = 16; o; o >>= 1) q2 += __shfl_xor_sync(0xffffffffu, q2, o);
    if (lane == 0) red[warp] = q2;
    __syncthreads();
    if (ft == 0) {
        float a = 0.f;
        for (int i = 0; i < 20; i++) a += red[i];
        mv[1] = rsqrtf(a * (1.0f / D) + 1e-5f);
    }
    __syncthreads();
    if (ft < D) xs[ft] = dv * mv[1] * lnw[ft] + lnb[ft];
    __syncthreads();
    // ---- phase 1: q projection (ty==0) and k255 projection (ty==1, self) ----
    {
        const float* W = ty ? Wk : Wq;
        if (ty == 0 || selfmode) {
            float acc = 0.f;
#pragma unroll 8
            for (int k = 0; k < D; k++) acc += xs[k] * W[k * D + tx];
            col[ty][tx] = acc + (ty ? bk[tx] : bq[tx]);
        }
    }
    __syncthreads();
    {
        int pp = (tx % HD) >> 1;
        if (ty == 0) {
            float e = col[0][tx & ~1] * 0.11180339887498949f;
            float o = col[0][tx | 1] * 0.11180339887498949f;
            float cc = g_qc[pp], ss = g_qs[pp];
            qs[tx] = (tx & 1) ? (o * cc + e * ss) : (e * cc - o * ss);
        } else if (selfmode) {
            float e = col[1][tx & ~1], o = col[1][tx | 1];
            float cc = g_rotc[TCACHE * HALF + pp], ss = g_rots[TCACHE * HALF + pp];
            k255[tx] = (tx & 1) ? (o * cc + e * ss) : (e * cc - o * ss);
        }
    }
    __syncthreads();
    // ---- phase 2: scores (20 warps x 13 rows) ----
    const float* K = (selfmode ? g_kself : g_kcross) + (long)l * NHYP * TK * D +
                     (long)h * TK * D;
#pragma unroll
    for (int i = 0; i < 13; i++) {
        int t = warp * 13 + i;
        if (t < TK) {
            bool use255 = selfmode && (t == TCACHE);
            const float* kr = use255 ? k255 : (K + (long)t * D);
            float sc[NH];
#pragma unroll
            for (int hh = 0; hh < NH; hh++) {
                int d0 = hh * HD + lane;
                float sv = qs[d0] * kr[d0] + qs[d0 + 32] * kr[d0 + 32];
                if (lane < 16) sv += qs[d0 + 64] * kr[d0 + 64];
                sc[hh] = sv;
            }
#pragma unroll
            for (int hh = 0; hh < NH; hh++)
#pragma unroll
                for (int o = 16; o; o >>= 1)
                    sc[hh] += __shfl_xor_sync(0xffffffffu, sc[hh], o);
            if (lane == 0) {
                bool msk = (mask != nullptr) && (mask[h * TK + t] != 0);
#pragma unroll
                for (int hh = 0; hh < NH; hh++) p[hh][t] = msk ? -1e30f : sc[hh];
            }
        }
    }
    __syncthreads();
    // ---- phase 3: softmax (2 passes, 2 heads per pass) ----
    for (int pass = 0; pass < 2; pass++) {
        bool act = (ft < 512);
        int grp = (ft >> 8) & 1;
        int hh = pass * 2 + grp;
        int t = ft & 255;
        float lv = act ? p[hh][t] : -1e30f;
        float m = lv;
#pragma unroll
        for (int o = 16; o; o >>= 1) m = fmaxf(m, __shfl_xor_sync(0xffffffffu, m, o));
        if (act && lane == 0) redv[grp][(ft >> 5) & 7] = m;
        __syncthreads();
        if (act && (ft & 255) == 0) {
            float mm = redv[grp][0];
            for (int j = 1; j < 8; j++) mm = fmaxf(mm, redv[grp][j]);
            val[grp] = mm;
        }
        __syncthreads();
        float ex = act ? expf(lv - val[grp]) : 0.f;
        float ssum = ex;
#pragma unroll
        for (int o = 16; o; o >>= 1) ssum += __shfl_xor_sync(0xffffffffu, ssum, o);
        if (act && lane == 0) redv[grp][(ft >> 5) & 7] = ssum;
        __syncthreads();
        if (act && (ft & 255) == 0) {
            float ss = 0.f;
            for (int j = 0; j < 8; j++) ss += redv[grp][j];
            val[grp] = ss;
        }
        __syncthreads();
        if (act) p[hh][t] = ex / val[grp];
        __syncthreads();
    }
    // ---- phase 4: LN fold (self) ----
    if (selfmode) {
        float c1 = 0.f;
        if (ft < 512) {
            int hh = ft >> 7, t0 = ft & 127;
            int r = loff + h * TCACHE;
            float p0 = p[hh][t0] * g_rs[r + t0];
            c1 = p0 * g_mu[r + t0];
            p[hh][t0] = p0;
            if (t0 < 127) {
                float p1 = p[hh][t0 + 128] * g_rs[r + t0 + 128];
                c1 += p1 * g_mu[r + t0 + 128];
                p[hh][t0 + 128] = p1;
            }
        }
#pragma unroll
        for (int o = 16; o; o >>= 1) c1 += __shfl_xor_sync(0xffffffffu, c1, o);
        if (ft < 512 && lane == 0) redc[ft >> 7][(ft >> 5) & 3] = c1;
        __syncthreads();
        if (ft < 512 && (ft & 127) == 0) {
            int hh = ft >> 7;
            corr[hh] = redc[hh][0] + redc[hh][1] + redc[hh][2] + redc[hh][3];
        }
        __syncthreads();
    }
    // ---- phase 5: y = p @ X ----
    {
        float a0 = 0.f, a1 = 0.f, a2 = 0.f, a3 = 0.f;
        int stride = selfmode ? TCACHE : TK;
        int tlo = ty * 128;
        int thi = ty ? stride : 128;
        const float* base = X + (long)h * stride * D + tx;
        for (int t = tlo; t < thi; t++) {
            float xv = base[(long)t * D];
            a0 += p[0][t] * xv;
            a1 += p[1][t] * xv;
            a2 += p[2][t] * xv;
            a3 += p[3][t] * xv;
        }
        py[ty][0][tx] = a0;
        py[ty][1][tx] = a1;
        py[ty][2][tx] = a2;
        py[ty][3][tx] = a3;
    }
    __syncthreads();
    if (ty == 0) {
        if (selfmode) {
            float w = lnw[tx], b = lnb[tx], nv = xs[tx];
#pragma unroll
            for (int hh = 0; hh < NH; hh++) {
                float a = py[0][hh][tx] + py[1][hh][tx];
                float pf = p[hh][TCACHE];
                ys[hh][tx] = (a - corr[hh]) * w + (1.f - pf) * b + pf * nv;
            }
        } else {
#pragma unroll
            for (int hh = 0; hh < NH; hh++) ys[hh][tx] = py[0][hh][tx] + py[1][hh][tx];
        }
    }
    __syncthreads();
    // ---- phase 6: z = y @ Wv + bv (per-head slice) ----
    {
        int hh = tx / HD;
        const float* yb = ys[hh];
        float z = 0.f;
        int d0 = ty * 160;
#pragma unroll 8
        for (int d2 = d0; d2 < d0 + 160; d2++) z += yb[d2] * Wv[d2 * D + tx];
        part[ty][tx] = z;
    }
    __syncthreads();
    if (ty == 0) qs[tx] = part[0][tx] + part[1][tx] + bv[tx];
    __syncthreads();
    // ---- phase 7: out = z @ Wo + bo; residual ----
    {
        float o = 0.f;
        int m0 = ty * 160;
#pragma unroll 8
        for (int m = m0; m < m0 + 160; m++) o += qs[m] * Wo[m * D + tx];
        part[ty][tx] = o;
    }
    __syncthreads();
    if (ty == 0) g_tgt[h * D + tx] += part[0][tx] + part[1][tx] + bo[tx];
}

// ---------------- FF1 with fused LN ----------------
__global__ void __launch_bounds__(256) k_ff1(const float* __restrict__ lnw,
                                             const float* __restrict__ lnb,
                                             const float* __restrict__ W1,
                                             const float* __restrict__ b1) {
    __shared__ float Aln[16][D + 1];
    __shared__ float Wsm[32][68];
    int h0 = blockIdx.x * 16, n0 = blockIdx.y * 64;
    int tid = threadIdx.x;
    int w = tid >> 5, lane = tid & 31;
#pragma unroll
    for (int rr = 0; rr < 2; rr++) {
        int row = w * 2 + rr;
        const float* src = g_tgt + (h0 + row) * D;
        float s = 0.f, s2 = 0.f;
        for (int j = lane; j < D; j += 32) {
            float x = src[j];
            s += x;
            s2 += x * x;
        }
#pragma unroll
        for (int o = 16; o; o >>= 1) {
            s += __shfl_xor_sync(0xffffffffu, s, o);
            s2 += __shfl_xor_sync(0xffffffffu, s2, o);
        }
        float mu = s * (1.0f / D);
        float rsd = rsqrtf(s2 * (1.0f / D) - mu * mu + 1e-5f);
        for (int j = lane; j < D; j += 32)
            Aln[row][j] = (src[j] - mu) * rsd * lnw[j] + lnb[j];
    }
    __syncthreads();
    int tx = tid & 15, ty = tid >> 4;
    float acc0 = 0.f, acc1 = 0.f, acc2 = 0.f, acc3 = 0.f;
    for (int k0 = 0; k0 < D; k0 += 32) {
#pragma unroll
        for (int i = 0; i < 2; i++) {
            int id2 = tid + 256 * i;
            int rr = id2 >> 4, c4 = (id2 & 15) * 4;
            float4 v = *(const float4*)&W1[(long)(k0 + rr) * FF + n0 + c4];
            Wsm[rr][c4 + 0] = v.x;
            Wsm[rr][c4 + 1] = v.y;
            Wsm[rr][c4 + 2] = v.z;
            Wsm[rr][c4 + 3] = v.w;
        }
        __syncthreads();
#pragma unroll
        for (int k = 0; k < 32; k++) {
            float a = Aln[ty][k0 + k];
            acc0 += a * Wsm[k][tx * 4 + 0];
            acc1 += a * Wsm[k][tx * 4 + 1];
            acc2 += a * Wsm[k][tx * 4 + 2];
            acc3 += a * Wsm[k][tx * 4 + 3];
        }
        __syncthreads();
    }
    int row = h0 + ty, n = n0 + tx * 4;
    float* op = &g_ff[(long)row * FF + n];
    op[0] = fmaxf(acc0 + b1[n + 0], 0.f);
    op[1] = fmaxf(acc1 + b1[n + 1], 0.f);
    op[2] = fmaxf(acc2 + b1[n + 2], 0.f);
    op[3] = fmaxf(acc3 + b1[n + 3], 0.f);
}

// ---------------- FF2 with K-split + atomicAdd ----------------
__global__ void __launch_bounds__(256) k_ff2(const float* __restrict__ W2,
                                             const float* __restrict__ b2) {
    __shared__ float Asm[16][33];
    __shared__ float Wsm[32][68];
    int h0 = blockIdx.x * 16, n0 = blockIdx.y * 64, kz = blockIdx.z;
    int tid = threadIdx.x, tx = tid & 15, ty = tid >> 4;
    float acc0 = 0.f, acc1 = 0.f, acc2 = 0.f, acc3 = 0.f;
    for (int k0 = kz * 512; k0 < kz * 512 + 512; k0 += 32) {
        {
            int r = tid >> 5, kk = tid & 31;
            Asm[r][kk] = g_ff[(long)(h0 + r) * FF + k0 + kk];
            Asm[r + 8][kk] = g_ff[(long)(h0 + r + 8) * FF + k0 + kk];
#pragma unroll
            for (int i = 0; i < 2; i++) {
                int id2 = tid + 256 * i;
                int rr = id2 >> 4, c4 = (id2 & 15) * 4;
                float4 v = *(const float4*)&W2[(long)(k0 + rr) * D + n0 + c4];
                Wsm[rr][c4 + 0] = v.x;
                Wsm[rr][c4 + 1] = v.y;
                Wsm[rr][c4 + 2] = v.z;
                Wsm[rr][c4 + 3] = v.w;
            }
        }
        __syncthreads();
#pragma unroll
        for (int k = 0; k < 32; k++) {
            float a = Asm[ty][k];
            acc0 += a * Wsm[k][tx * 4 + 0];
            acc1 += a * Wsm[k][tx * 4 + 1];
            acc2 += a * Wsm[k][tx * 4 + 2];
            acc3 += a * Wsm[k][tx * 4 + 3];
        }
        __syncthreads();
    }
    int row = h0 + ty, n = n0 + tx * 4;
    if (kz == 0) {
        acc0 += b2[n + 0];
        acc1 += b2[n + 1];
        acc2 += b2[n + 2];
        acc3 += b2[n + 3];
    }
    atomicAdd(&g_tgt[row * D + n + 0], acc0);
    atomicAdd(&g_tgt[row * D + n + 1], acc1);
    atomicAdd(&g_tgt[row * D + n + 2], acc2);
    atomicAdd(&g_tgt[row * D + n + 3], acc3);
}

__global__ void k_copy_out(float* __restrict__ out) {
    out[blockIdx.x * D + threadIdx.x] = g_tgt[blockIdx.x * D + threadIdx.x];
}

// ---------------- launch (kernel launches ONLY, default stream) ----------------
extern "C" void kernel_launch(void* const* d_in, const int* in_sizes, int n_in,
                              void* d_out, int out_size) {
    const int* toks = (const int*)d_in[0];
    const float* cached = (const float*)d_in[1];
    const float* memory = (const float*)d_in[2];
    const unsigned char* mmask = (const unsigned char*)d_in[3];
    const int* qoff = (const int*)d_in[4];
    const float* table = (const float*)d_in[5];
    const float* ln_w = (const float*)d_in[6];
    const float* ln_b = (const float*)d_in[7];
    const float* sa_w = (const float*)d_in[8];
    const float* sa_b = (const float*)d_in[9];
    const float* ca_w = (const float*)d_in[10];
    const float* ca_b = (const float*)d_in[11];
    const float* ff1w = (const float*)d_in[12];
    const float* ff1b = (const float*)d_in[13];
    const float* ff2w = (const float*)d_in[14];
    const float* ff2b = (const float*)d_in[15];

    k_tables<<<41, 256>>>(qoff);
    k_embed<<<NHYP, D>>>(toks, table);
    k_rowstats<<<(NL * NHYP * TCACHE + 7) / 8, 256>>>(cached);
    k_gemm_all<<<dim3(128, 5, 10), 256>>>(cached, memory, ln_w, ln_b, sa_w, sa_b,
                                          ca_w, ca_b);

    for (int l = 0; l < NL; l++) {
        const float* lw = ln_w + l * 3 * D;
        const float* lb = ln_b + l * 3 * D;
        const float* sw = sa_w + (long)l * 4 * D * D;
        const float* sb = sa_b + l * 4 * D;
        const float* cw = ca_w + (long)l * 4 * D * D;
        const float* cb = ca_b + l * 4 * D;
        const float* cache_l = cached + (long)l * NHYP * TCACHE * D;
        int loff = l * NHYP * TCACHE;

        // ---- self-attention (fully fused) ----
        k_attn_full<<<NHYP, dim3(320, 2)>>>(
            cache_l, 1, loff, l, lw, lb, nullptr,
            sw + 0 * D * D, sb + 0 * D, sw + 1 * D * D, sb + 1 * D,
            sw + 2 * D * D, sb + 2 * D, sw + 3 * D * D, sb + 3 * D);
        // ---- cross-attention (fully fused) ----
        k_attn_full<<<NHYP, dim3(320, 2)>>>(
            memory, 0, 0, l, lw + D, lb + D, mmask,
            cw + 0 * D * D, cb + 0 * D, nullptr, nullptr,
            cw + 2 * D * D, cb + 2 * D, cw + 3 * D * D, cb + 3 * D);
        // ---- feed-forward ----
        k_ff1<<<dim3(4, FF / 64), 256>>>(lw + 2 * D, lb + 2 * D,
                                         ff1w + (long)l * D * FF, ff1b + l * FF);
        k_ff2<<<dim3(4, 5, 4), 256>>>(ff2w + (long)l * FF * D, ff2b + l * D);
    }
    k_copy_out<<<NHYP, D>>>((float*)d_out);
}

// round 12
// speedup vs baseline: 1.0708x; 1.0708x over previous
#include <cuda_runtime.h>
#include <math.h>
#include <stdint.h>

#define NHYP 64
#define D 320
#define NH 4
#define HD 80
#define HALF 40
#define TK 256
#define TCACHE 255
#define FF 2048
#define NL 5

// ---------------- scratch (device globals) ----------------
__device__ float g_tgt[NHYP * D];
__device__ float g_nt0[NHYP * D];
__device__ float g_kself[NL * NHYP * TK * D];
__device__ float g_kcross[NL * NHYP * TK * D];
__device__ float g_q[NHYP * D];
__device__ float g_ff[NHYP * FF];
__device__ float g_mu[NL * NHYP * TCACHE];
__device__ float g_rs[NL * NHYP * TCACHE];
__device__ float g_rotc[TK * HALF];
__device__ float g_rots[TK * HALF];
__device__ float g_qc[HALF];
__device__ float g_qs[HALF];

// ---------------- helpers ----------------
__device__ __forceinline__ uint32_t f2tf(float f) {
    uint32_t u;
    asm("cvt.rna.tf32.f32 %0, %1;" : "=r"(u) : "f"(f));
    return u;
}
__device__ __forceinline__ void mma_tf32(float* d, const uint32_t* a, const uint32_t* b) {
    asm volatile(
        "mma.sync.aligned.m16n8k8.row.col.f32.tf32.tf32.f32 "
        "{%0,%1,%2,%3}, {%4,%5,%6,%7}, {%8,%9}, {%0,%1,%2,%3};"
        : "+f"(d[0]), "+f"(d[1]), "+f"(d[2]), "+f"(d[3])
        : "r"(a[0]), "r"(a[1]), "r"(a[2]), "r"(a[3]), "r"(b[0]), "r"(b[1]));
}

// ---------------- xPos tables ----------------
__global__ void k_tables(const int* __restrict__ qoff) {
    int e = blockIdx.x * blockDim.x + threadIdx.x;
    if (e < TK * HALF) {
        int t = e / HALF, i = e % HALF;
        float bs = (2.0f * i + 0.4f * HD) / (1.4f * HD);
        float invf = powf(10000.0f, -(float)i / HALF);
        float power = ((float)t - 128.0f) / 320.0f;
        float z = powf(bs, -power);
        float th = (float)t * invf;
        g_rotc[e] = cosf(th) * z;
        g_rots[e] = sinf(th) * z;
    } else if (e < TK * HALF + HALF) {
        int i = e - TK * HALF;
        int off = qoff[0];
        int total = off + 1;
        int minp = -((total + 1) >> 1);
        float bs = (2.0f * i + 0.4f * HD) / (1.4f * HD);
        float invf = powf(10000.0f, -(float)i / HALF);
        float pq = (float)(minp + total - 1) / 320.0f;
        float z = powf(bs, pq);
        float th = (float)(total - 1) * invf;
        g_qc[i] = cosf(th) * z;
        g_qs[i] = sinf(th) * z;
    }
}

__global__ void k_embed(const int* __restrict__ toks, const float* __restrict__ table) {
    int h = blockIdx.x, d = threadIdx.x;
    g_tgt[h * D + d] = table[(long)toks[h] * D + d];
}

__global__ void k_rowstats(const float* __restrict__ cached) {
    int row = blockIdx.x * 8 + (threadIdx.x >> 5);
    if (row >= NL * NHYP * TCACHE) return;
    int lane = threadIdx.x & 31;
    const float* p = cached + (long)row * D;
    float s = 0.f, s2 = 0.f;
    for (int j = lane; j < D; j += 32) {
        float v = p[j];
        s += v;
        s2 += v * v;
    }
#pragma unroll
    for (int o = 16; o; o >>= 1) {
        s += __shfl_xor_sync(0xffffffffu, s, o);
        s2 += __shfl_xor_sync(0xffffffffu, s2, o);
    }
    if (lane == 0) {
        float mu = s * (1.0f / D);
        float var = s2 * (1.0f / D) - mu * mu;
        g_mu[row] = mu;
        g_rs[row] = rsqrtf(var + 1e-5f);
    }
}

// ---------------- batched K-projection GEMM (all 10): R4 layout + register pipeline ----
// grid (128, 5, 10), 256 threads. Block tile 128x64, warp tile 32x32.
#define GBM 128
#define GBN 64
#define GBK 32
__global__ void __launch_bounds__(256) k_gemm_all(
    const float* __restrict__ cached, const float* __restrict__ memory,
    const float* __restrict__ ln_w, const float* __restrict__ ln_b,
    const float* __restrict__ sa_w, const float* __restrict__ sa_b,
    const float* __restrict__ ca_w, const float* __restrict__ ca_b) {
    __shared__ uint32_t As[GBM][GBK + 4];
    __shared__ uint32_t Bs[GBK][GBN + 8];
    __shared__ float sw[D], sb[D];
    int z = blockIdx.z;
    bool selfmode = (z < 5);
    int l = selfmode ? z : z - 5;
    const float* Araw = selfmode ? cached + (long)l * NHYP * TCACHE * D : memory;
    const float* B = (selfmode ? sa_w : ca_w) + (long)l * 4 * D * D + D * D;
    const float* bias = (selfmode ? sa_b : ca_b) + l * 4 * D + D;
    float* out = (selfmode ? g_kself : g_kcross) + (long)l * NHYP * TK * D;
    int loff = l * NHYP * TCACHE;
    int tid = threadIdx.x;
    if (selfmode) {
        const float* lw = ln_w + l * 3 * D;
        const float* lb = ln_b + l * 3 * D;
        for (int i = tid; i < D; i += 256) {
            sw[i] = lw[i];
            sb[i] = lb[i];
        }
    }
    __syncthreads();
    int m0 = blockIdx.x * GBM, n0 = blockIdx.y * GBN;
    int warp = tid >> 5, lane = tid & 31;
    int wm = warp >> 1, wn = warp & 1;
    int g = lane >> 2, c = lane & 3;
    float acc[2][4][4];
#pragma unroll
    for (int a = 0; a < 2; a++)
#pragma unroll
        for (int bb = 0; bb < 4; bb++)
#pragma unroll
            for (int cc = 0; cc < 4; cc++) acc[a][bb][cc] = 0.f;

    // per-thread fixed load coordinates
    int arow[4], ac4[4], at[4], ar[4];
#pragma unroll
    for (int i = 0; i < 4; i++) {
        int idx = tid + 256 * i;
        arow[i] = idx >> 3;
        ac4[i] = (idx & 7) * 4;
        int m = m0 + arow[i];
        at[i] = m & 255;
        ar[i] = (m >> 8) * TCACHE + at[i];
    }
    int bk_[2], bn4[2];
#pragma unroll
    for (int i = 0; i < 2; i++) {
        int idx = tid + 256 * i;
        bk_[i] = idx >> 4;
        bn4[i] = (idx & 15) * 4;
    }

    float4 va[4], vb[2];
    float muR[4], rsR[4];

    // ---- prefetch tile k0=0 ----
#pragma unroll
    for (int i = 0; i < 4; i++) {
        va[i] = make_float4(0.f, 0.f, 0.f, 0.f);
        muR[i] = 0.f;
        rsR[i] = 0.f;
        if (selfmode) {
            if (at[i] < TCACHE) {
                va[i] = *(const float4*)&Araw[(long)ar[i] * D + ac4[i]];
                muR[i] = g_mu[loff + ar[i]];
                rsR[i] = g_rs[loff + ar[i]];
            }
        } else {
            va[i] = *(const float4*)&Araw[(long)(m0 + arow[i]) * D + ac4[i]];
        }
    }
#pragma unroll
    for (int i = 0; i < 2; i++)
        vb[i] = *(const float4*)&B[(long)bk_[i] * D + n0 + bn4[i]];

    for (int k0 = 0; k0 < D; k0 += GBK) {
        // ---- store staged tile to smem (fold LN for self) ----
#pragma unroll
        for (int i = 0; i < 4; i++) {
            float4 v = va[i];
            if (selfmode && at[i] < TCACHE) {
                float m_ = muR[i], rr = rsR[i];
                v.x = (v.x - m_) * rr * sw[k0 + ac4[i] + 0] + sb[k0 + ac4[i] + 0];
                v.y = (v.y - m_) * rr * sw[k0 + ac4[i] + 1] + sb[k0 + ac4[i] + 1];
                v.z = (v.z - m_) * rr * sw[k0 + ac4[i] + 2] + sb[k0 + ac4[i] + 2];
                v.w = (v.w - m_) * rr * sw[k0 + ac4[i] + 3] + sb[k0 + ac4[i] + 3];
            }
            As[arow[i]][ac4[i] + 0] = f2tf(v.x);
            As[arow[i]][ac4[i] + 1] = f2tf(v.y);
            As[arow[i]][ac4[i] + 2] = f2tf(v.z);
            As[arow[i]][ac4[i] + 3] = f2tf(v.w);
        }
#pragma unroll
        for (int i = 0; i < 2; i++) {
            Bs[bk_[i]][bn4[i] + 0] = f2tf(vb[i].x);
            Bs[bk_[i]][bn4[i] + 1] = f2tf(vb[i].y);
            Bs[bk_[i]][bn4[i] + 2] = f2tf(vb[i].z);
            Bs[bk_[i]][bn4[i] + 3] = f2tf(vb[i].w);
        }
        __syncthreads();
        // ---- prefetch next tile while MMAs run ----
        int kn = k0 + GBK;
        if (kn < D) {
#pragma unroll
            for (int i = 0; i < 4; i++) {
                if (selfmode) {
                    if (at[i] < TCACHE)
                        va[i] = *(const float4*)&Araw[(long)ar[i] * D + kn + ac4[i]];
                } else {
                    va[i] = *(const float4*)&Araw[(long)(m0 + arow[i]) * D + kn + ac4[i]];
                }
            }
#pragma unroll
            for (int i = 0; i < 2; i++)
                vb[i] = *(const float4*)&B[(long)(kn + bk_[i]) * D + n0 + bn4[i]];
        }
        // ---- MMA phase ----
#pragma unroll
        for (int ks = 0; ks < 4; ks++) {
            uint32_t afr[2][4], bfr[4][2];
#pragma unroll
            for (int mi = 0; mi < 2; mi++) {
                int r = wm * 32 + mi * 16;
                afr[mi][0] = As[r + g][ks * 8 + c];
                afr[mi][1] = As[r + g + 8][ks * 8 + c];
                afr[mi][2] = As[r + g][ks * 8 + c + 4];
                afr[mi][3] = As[r + g + 8][ks * 8 + c + 4];
            }
#pragma unroll
            for (int ni = 0; ni < 4; ni++) {
                int nn = wn * 32 + ni * 8;
                bfr[ni][0] = Bs[ks * 8 + c][nn + g];
                bfr[ni][1] = Bs[ks * 8 + c + 4][nn + g];
            }
#pragma unroll
            for (int mi = 0; mi < 2; mi++)
#pragma unroll
                for (int ni = 0; ni < 4; ni++) mma_tf32(acc[mi][ni], afr[mi], bfr[ni]);
        }
        __syncthreads();
    }
    // ---- epilogue: bias + rotation ----
#pragma unroll
    for (int mi = 0; mi < 2; mi++) {
        int r0 = m0 + wm * 32 + mi * 16 + g;
        int r1 = r0 + 8;
        int t0 = r0 & 255, t1 = r1 & 255;
#pragma unroll
        for (int ni = 0; ni < 4; ni++) {
            int nn = n0 + wn * 32 + ni * 8 + 2 * c;
            int p = (nn % HD) >> 1;
            float be = bias[nn], bo = bias[nn + 1];
            {
                float cc = g_rotc[t0 * HALF + p], ss = g_rots[t0 * HALF + p];
                float e = acc[mi][ni][0] + be, o = acc[mi][ni][1] + bo;
                *(float2*)&out[(long)r0 * D + nn] =
                    make_float2(e * cc - o * ss, o * cc + e * ss);
            }
            {
                float cc = g_rotc[t1 * HALF + p], ss = g_rots[t1 * HALF + p];
                float e = acc[mi][ni][2] + be, o = acc[mi][ni][3] + bo;
                *(float2*)&out[(long)r1 * D + nn] =
                    make_float2(e * cc - o * ss, o * cc + e * ss);
            }
        }
    }
}

// ---------------- fused LN + q-proj (+ k255-proj for self) ----------------
// grid (64, 2, selfmode?2:1), block (160, 4)
__global__ void k_qk(int selfmode, int l,
                     const float* __restrict__ lnw, const float* __restrict__ lnb,
                     const float* __restrict__ Wq, const float* __restrict__ bq,
                     const float* __restrict__ Wk, const float* __restrict__ bk) {
    __shared__ float xs[D];
    __shared__ float part[4][160];
    __shared__ float qv[160];
    __shared__ float red[20];
    __shared__ float mv[2];
    int h = blockIdx.x, tx = threadIdx.x, ty = threadIdx.y;
    int ft = ty * 160 + tx;
    int lane = ft & 31, warp = ft >> 5;
    float v = (ft < D) ? g_tgt[h * D + ft] : 0.f;
    float s = v;
#pragma unroll
    for (int o = 16; o; o >>= 1) s += __shfl_xor_sync(0xffffffffu, s, o);
    if (lane == 0) red[warp] = s;
    __syncthreads();
    if (ft == 0) {
        float a = 0.f;
        for (int i = 0; i < 20; i++) a += red[i];
        mv[0] = a * (1.0f / D);
    }
    __syncthreads();
    float mu = mv[0];
    float dv = v - mu;
    float q2 = (ft < D) ? dv * dv : 0.f;
#pragma unroll
    for (int o = 16; o; o >>= 1) q2 += __shfl_xor_sync(0xffffffffu, q2, o);
    if (lane == 0) red[warp] = q2;
    __syncthreads();
    if (ft == 0) {
        float a = 0.f;
        for (int i = 0; i < 20; i++) a += red[i];
        mv[1] = rsqrtf(a * (1.0f / D) + 1e-5f);
    }
    __syncthreads();
    if (ft < D) xs[ft] = dv * mv[1] * lnw[ft] + lnb[ft];
    __syncthreads();
    if (selfmode && blockIdx.y == 0 && blockIdx.z == 0 && ft < D)
        g_nt0[h * D + ft] = xs[ft];
    const float* W = (blockIdx.z == 0) ? Wq : Wk;
    const float* bias = (blockIdx.z == 0) ? bq : bk;
    int n = blockIdx.y * 160 + tx;
    float acc = 0.f;
    int k0 = ty * 80;
#pragma unroll 8
    for (int k = k0; k < k0 + 80; k++) acc += xs[k] * W[k * D + n];
    part[ty][tx] = acc;
    __syncthreads();
    if (ty == 0) {
        float t = part[0][tx] + part[1][tx] + part[2][tx] + part[3][tx] + bias[n];
        qv[tx] = (blockIdx.z == 0) ? t * 0.11180339887498949f : t;
    }
    __syncthreads();
    if (ty == 0) {
        int p = (n % HD) >> 1;
        float cc, ss;
        if (blockIdx.z == 0) {
            cc = g_qc[p];
            ss = g_qs[p];
        } else {
            cc = g_rotc[TCACHE * HALF + p];
            ss = g_rots[TCACHE * HALF + p];
        }
        float e = qv[tx & ~1], o = qv[tx | 1];
        float r = (n & 1) ? (o * cc + e * ss) : (e * cc - o * ss);
        if (blockIdx.z == 0)
            g_q[h * D + n] = r;
        else
            g_kself[(long)l * NHYP * TK * D + ((long)h * TK + TCACHE) * D + n] = r;
    }
}

// ---------------- fused attention + out-projection ----------------
// grid 64, block (320, 2)
__global__ void k_attn_out(const float* __restrict__ X, int selfmode, int loff, int l,
                           const float* __restrict__ lnw, const float* __restrict__ lnb,
                           const unsigned char* __restrict__ mask,
                           const float* __restrict__ Wv, const float* __restrict__ bv,
                           const float* __restrict__ Wo, const float* __restrict__ bo) {
    __shared__ float qs[D];
    __shared__ float p[NH][TK];
    __shared__ float ys[NH][D];
    __shared__ float py[2][NH][D];
    __shared__ float part[2][D];
    __shared__ float red[2][8];
    __shared__ float val[2];
    __shared__ float redc[4][4];
    __shared__ float corr[NH];
    int h = blockIdx.x, tx = threadIdx.x, ty = threadIdx.y;
    int ft = ty * 320 + tx;
    int warp = ft >> 5, lane = ft & 31;
    const float* K = (selfmode ? g_kself : g_kcross) + (long)l * NHYP * TK * D +
                     (long)h * TK * D;
    if (ty == 0) qs[tx] = g_q[h * D + tx];
    __syncthreads();
#pragma unroll
    for (int i = 0; i < 13; i++) {
        int t = warp * 13 + i;
        if (t < TK) {
            const float* kr = K + (long)t * D;
            float sc[NH];
#pragma unroll
            for (int hh = 0; hh < NH; hh++) {
                int d0 = hh * HD + lane;
                float s = qs[d0] * kr[d0] + qs[d0 + 32] * kr[d0 + 32];
                if (lane < 16) s += qs[d0 + 64] * kr[d0 + 64];
                sc[hh] = s;
            }
#pragma unroll
            for (int hh = 0; hh < NH; hh++)
#pragma unroll
                for (int o = 16; o; o >>= 1)
                    sc[hh] += __shfl_xor_sync(0xffffffffu, sc[hh], o);
            if (lane == 0) {
                bool msk = (mask != nullptr) && (mask[h * TK + t] != 0);
#pragma unroll
                for (int hh = 0; hh < NH; hh++) p[hh][t] = msk ? -1e30f : sc[hh];
            }
        }
    }
    __syncthreads();
    for (int pass = 0; pass < 2; pass++) {
        bool act = (ft < 512);
        int grp = (ft >> 8) & 1;
        int hh = pass * 2 + grp;
        int t = ft & 255;
        float lv = act ? p[hh][t] : -1e30f;
        float m = lv;
#pragma unroll
        for (int o = 16; o; o >>= 1) m = fmaxf(m, __shfl_xor_sync(0xffffffffu, m, o));
        if (act && lane == 0) red[grp][(ft >> 5) & 7] = m;
        __syncthreads();
        if (act && (ft & 255) == 0) {
            float mm = red[grp][0];
            for (int j = 1; j < 8; j++) mm = fmaxf(mm, red[grp][j]);
            val[grp] = mm;
        }
        __syncthreads();
        float ex = act ? expf(lv - val[grp]) : 0.f;
        float ssum = ex;
#pragma unroll
        for (int o = 16; o; o >>= 1) ssum += __shfl_xor_sync(0xffffffffu, ssum, o);
        if (act && lane == 0) red[grp][(ft >> 5) & 7] = ssum;
        __syncthreads();
        if (act && (ft & 255) == 0) {
            float ss = 0.f;
            for (int j = 0; j < 8; j++) ss += red[grp][j];
            val[grp] = ss;
        }
        __syncthreads();
        if (act) p[hh][t] = ex / val[grp];
        __syncthreads();
    }
    if (selfmode) {
        float c1 = 0.f;
        if (ft < 512) {
            int hh = ft >> 7, t0 = ft & 127;
            int r = loff + h * TCACHE;
            float p0 = p[hh][t0] * g_rs[r + t0];
            c1 = p0 * g_mu[r + t0];
            p[hh][t0] = p0;
            if (t0 < 127) {
                float p1 = p[hh][t0 + 128] * g_rs[r + t0 + 128];
                c1 += p1 * g_mu[r + t0 + 128];
                p[hh][t0 + 128] = p1;
            }
        }
#pragma unroll
        for (int o = 16; o; o >>= 1) c1 += __shfl_xor_sync(0xffffffffu, c1, o);
        if (ft < 512 && lane == 0) redc[ft >> 7][(ft >> 5) & 3] = c1;
        __syncthreads();
        if (ft < 512 && (ft & 127) == 0) {
            int hh = ft >> 7;
            corr[hh] = redc[hh][0] + redc[hh][1] + redc[hh][2] + redc[hh][3];
        }
        __syncthreads();
    }
    {
        float a0 = 0.f, a1 = 0.f, a2 = 0.f, a3 = 0.f;
        int stride = selfmode ? TCACHE : TK;
        int tlo = ty * 128;
        int thi = ty ? stride : 128;
        const float* base = X + (long)h * stride * D + tx;
        for (int t = tlo; t < thi; t++) {
            float xv = base[(long)t * D];
            a0 += p[0][t] * xv;
            a1 += p[1][t] * xv;
            a2 += p[2][t] * xv;
            a3 += p[3][t] * xv;
        }
        py[ty][0][tx] = a0;
        py[ty][1][tx] = a1;
        py[ty][2][tx] = a2;
        py[ty][3][tx] = a3;
    }
    __syncthreads();
    if (ty == 0) {
        if (selfmode) {
            float w = lnw[tx], b = lnb[tx], nv = g_nt0[h * D + tx];
#pragma unroll
            for (int hh = 0; hh < NH; hh++) {
                float a = py[0][hh][tx] + py[1][hh][tx];
                float pf = p[hh][TCACHE];
                ys[hh][tx] = (a - corr[hh]) * w + (1.f - pf) * b + pf * nv;
            }
        } else {
#pragma unroll
            for (int hh = 0; hh < NH; hh++) ys[hh][tx] = py[0][hh][tx] + py[1][hh][tx];
        }
    }
    __syncthreads();
    {
        int hh = tx / HD;
        const float* yb = ys[hh];
        float z = 0.f;
        int d0 = ty * 160;
#pragma unroll 8
        for (int d2 = d0; d2 < d0 + 160; d2++) z += yb[d2] * Wv[d2 * D + tx];
        part[ty][tx] = z;
    }
    __syncthreads();
    if (ty == 0) qs[tx] = part[0][tx] + part[1][tx] + bv[tx];
    __syncthreads();
    {
        float o = 0.f;
        int m0 = ty * 160;
#pragma unroll 8
        for (int m = m0; m < m0 + 160; m++) o += qs[m] * Wo[m * D + tx];
        part[ty][tx] = o;
    }
    __syncthreads();
    if (ty == 0) g_tgt[h * D + tx] += part[0][tx] + part[1][tx] + bo[tx];
}

// ---------------- FF1 with fused LN ----------------
__global__ void __launch_bounds__(256) k_ff1(const float* __restrict__ lnw,
                                             const float* __restrict__ lnb,
                                             const float* __restrict__ W1,
                                             const float* __restrict__ b1) {
    __shared__ float Aln[16][D + 1];
    __shared__ float Wsm[32][68];
    int h0 = blockIdx.x * 16, n0 = blockIdx.y * 64;
    int tid = threadIdx.x;
    int w = tid >> 5, lane = tid & 31;
#pragma unroll
    for (int rr = 0; rr < 2; rr++) {
        int row = w * 2 + rr;
        const float* src = g_tgt + (h0 + row) * D;
        float s = 0.f, s2 = 0.f;
        for (int j = lane; j < D; j += 32) {
            float x = src[j];
            s += x;
            s2 += x * x;
        }
#pragma unroll
        for (int o = 16; o; o >>= 1) {
            s += __shfl_xor_sync(0xffffffffu, s, o);
            s2 += __shfl_xor_sync(0xffffffffu, s2, o);
        }
        float mu = s * (1.0f / D);
        float rsd = rsqrtf(s2 * (1.0f / D) - mu * mu + 1e-5f);
        for (int j = lane; j < D; j += 32)
            Aln[row][j] = (src[j] - mu) * rsd * lnw[j] + lnb[j];
    }
    __syncthreads();
    int tx = tid & 15, ty = tid >> 4;
    float acc0 = 0.f, acc1 = 0.f, acc2 = 0.f, acc3 = 0.f;
    for (int k0 = 0; k0 < D; k0 += 32) {
#pragma unroll
        for (int i = 0; i < 2; i++) {
            int id2 = tid + 256 * i;
            int rr = id2 >> 4, c4 = (id2 & 15) * 4;
            float4 v = *(const float4*)&W1[(long)(k0 + rr) * FF + n0 + c4];
            Wsm[rr][c4 + 0] = v.x;
            Wsm[rr][c4 + 1] = v.y;
            Wsm[rr][c4 + 2] = v.z;
            Wsm[rr][c4 + 3] = v.w;
        }
        __syncthreads();
#pragma unroll
        for (int k = 0; k < 32; k++) {
            float a = Aln[ty][k0 + k];
            acc0 += a * Wsm[k][tx * 4 + 0];
            acc1 += a * Wsm[k][tx * 4 + 1];
            acc2 += a * Wsm[k][tx * 4 + 2];
            acc3 += a * Wsm[k][tx * 4 + 3];
        }
        __syncthreads();
    }
    int row = h0 + ty, n = n0 + tx * 4;
    float* op = &g_ff[(long)row * FF + n];
    op[0] = fmaxf(acc0 + b1[n + 0], 0.f);
    op[1] = fmaxf(acc1 + b1[n + 1], 0.f);
    op[2] = fmaxf(acc2 + b1[n + 2], 0.f);
    op[3] = fmaxf(acc3 + b1[n + 3], 0.f);
}

// ---------------- FF2 with K-split + atomicAdd ----------------
__global__ void __launch_bounds__(256) k_ff2(const float* __restrict__ W2,
                                             const float* __restrict__ b2) {
    __shared__ float Asm[16][33];
    __shared__ float Wsm[32][68];
    int h0 = blockIdx.x * 16, n0 = blockIdx.y * 64, kz = blockIdx.z;
    int tid = threadIdx.x, tx = tid & 15, ty = tid >> 4;
    float acc0 = 0.f, acc1 = 0.f, acc2 = 0.f, acc3 = 0.f;
    for (int k0 = kz * 512; k0 < kz * 512 + 512; k0 += 32) {
        {
            int r = tid >> 5, kk = tid & 31;
            Asm[r][kk] = g_ff[(long)(h0 + r) * FF + k0 + kk];
            Asm[r + 8][kk] = g_ff[(long)(h0 + r + 8) * FF + k0 + kk];
#pragma unroll
            for (int i = 0; i < 2; i++) {
                int id2 = tid + 256 * i;
                int rr = id2 >> 4, c4 = (id2 & 15) * 4;
                float4 v = *(const float4*)&W2[(long)(k0 + rr) * D + n0 + c4];
                Wsm[rr][c4 + 0] = v.x;
                Wsm[rr][c4 + 1] = v.y;
                Wsm[rr][c4 + 2] = v.z;
                Wsm[rr][c4 + 3] = v.w;
            }
        }
        __syncthreads();
#pragma unroll
        for (int k = 0; k < 32; k++) {
            float a = Asm[ty][k];
            acc0 += a * Wsm[k][tx * 4 + 0];
            acc1 += a * Wsm[k][tx * 4 + 1];
            acc2 += a * Wsm[k][tx * 4 + 2];
            acc3 += a * Wsm[k][tx * 4 + 3];
        }
        __syncthreads();
    }
    int row = h0 + ty, n = n0 + tx * 4;
    if (kz == 0) {
        acc0 += b2[n + 0];
        acc1 += b2[n + 1];
        acc2 += b2[n + 2];
        acc3 += b2[n + 3];
    }
    atomicAdd(&g_tgt[row * D + n + 0], acc0);
    atomicAdd(&g_tgt[row * D + n + 1], acc1);
    atomicAdd(&g_tgt[row * D + n + 2], acc2);
    atomicAdd(&g_tgt[row * D + n + 3], acc3);
}

__global__ void k_copy_out(float* __restrict__ out) {
    out[blockIdx.x * D + threadIdx.x] = g_tgt[blockIdx.x * D + threadIdx.x];
}

// ---------------- launch (kernel launches ONLY, default stream) ----------------
extern "C" void kernel_launch(void* const* d_in, const int* in_sizes, int n_in,
                              void* d_out, int out_size) {
    const int* toks = (const int*)d_in[0];
    const float* cached = (const float*)d_in[1];
    const float* memory = (const float*)d_in[2];
    const unsigned char* mmask = (const unsigned char*)d_in[3];
    const int* qoff = (const int*)d_in[4];
    const float* table = (const float*)d_in[5];
    const float* ln_w = (const float*)d_in[6];
    const float* ln_b = (const float*)d_in[7];
    const float* sa_w = (const float*)d_in[8];
    const float* sa_b = (const float*)d_in[9];
    const float* ca_w = (const float*)d_in[10];
    const float* ca_b = (const float*)d_in[11];
    const float* ff1w = (const float*)d_in[12];
    const float* ff1b = (const float*)d_in[13];
    const float* ff2w = (const float*)d_in[14];
    const float* ff2b = (const float*)d_in[15];

    k_tables<<<41, 256>>>(qoff);
    k_embed<<<NHYP, D>>>(toks, table);
    k_rowstats<<<(NL * NHYP * TCACHE + 7) / 8, 256>>>(cached);
    k_gemm_all<<<dim3(128, 5, 10), 256>>>(cached, memory, ln_w, ln_b, sa_w, sa_b,
                                          ca_w, ca_b);

    for (int l = 0; l < NL; l++) {
        const float* lw = ln_w + l * 3 * D;
        const float* lb = ln_b + l * 3 * D;
        const float* sw = sa_w + (long)l * 4 * D * D;
        const float* sb = sa_b + l * 4 * D;
        const float* cw = ca_w + (long)l * 4 * D * D;
        const float* cb = ca_b + l * 4 * D;
        const float* cache_l = cached + (long)l * NHYP * TCACHE * D;
        int loff = l * NHYP * TCACHE;

        // ---- self-attention ----
        k_qk<<<dim3(NHYP, 2, 2), dim3(160, 4)>>>(1, l, lw, lb, sw, sb,
                                                 sw + D * D, sb + D);
        k_attn_out<<<NHYP, dim3(320, 2)>>>(cache_l, 1, loff, l, lw, lb, nullptr,
                                           sw + 2 * D * D, sb + 2 * D,
                                           sw + 3 * D * D, sb + 3 * D);
        // ---- cross-attention ----
        k_qk<<<dim3(NHYP, 2, 1), dim3(160, 4)>>>(0, l, lw + D, lb + D, cw, cb,
                                                 nullptr, nullptr);
        k_attn_out<<<NHYP, dim3(320, 2)>>>(memory, 0, 0, l, nullptr, nullptr, mmask,
                                           cw + 2 * D * D, cb + 2 * D,
                                           cw + 3 * D * D, cb + 3 * D);
        // ---- feed-forward ----
        k_ff1<<<dim3(4, FF / 64), 256>>>(lw + 2 * D, lb + 2 * D,
                                         ff1w + (long)l * D * FF, ff1b + l * FF);
        k_ff2<<<dim3(4, 5, 4), 256>>>(ff2w + (long)l * FF * D, ff2b + l * D);
    }
    k_copy_out<<<NHYP, D>>>((float*)d_out);
}

// round 14
// speedup vs baseline: 1.2425x; 1.1603x over previous
#include <cuda_runtime.h>
#include <math.h>
#include <stdint.h>

#define NHYP 64
#define D 320
#define NH 4
#define HD 80
#define HALF 40
#define TK 256
#define TCACHE 255
#define FF 2048
#define NL 5

// ---------------- scratch (device globals) ----------------
__device__ float g_tgt[NHYP * D];
__device__ float g_nt0[NHYP * D];
__device__ float g_kself[NL * NHYP * TK * D];
__device__ float g_kcross[NL * NHYP * TK * D];
__device__ float g_q[NHYP * D];
__device__ float g_ff[NHYP * FF];
__device__ float g_mu[NL * NHYP * TCACHE];
__device__ float g_rs[NL * NHYP * TCACHE];
__device__ float g_rotc[TK * HALF];
__device__ float g_rots[TK * HALF];
__device__ float g_qc[HALF];
__device__ float g_qs[HALF];

// ---------------- helpers ----------------
__device__ __forceinline__ uint32_t f2tf(float f) {
    uint32_t u;
    asm("cvt.rna.tf32.f32 %0, %1;" : "=r"(u) : "f"(f));
    return u;
}
__device__ __forceinline__ void mma_tf32(float* d, const uint32_t* a, const uint32_t* b) {
    asm volatile(
        "mma.sync.aligned.m16n8k8.row.col.f32.tf32.tf32.f32 "
        "{%0,%1,%2,%3}, {%4,%5,%6,%7}, {%8,%9}, {%0,%1,%2,%3};"
        : "+f"(d[0]), "+f"(d[1]), "+f"(d[2]), "+f"(d[3])
        : "r"(a[0]), "r"(a[1]), "r"(a[2]), "r"(a[3]), "r"(b[0]), "r"(b[1]));
}

// ---------------- xPos tables ----------------
__global__ void k_tables(const int* __restrict__ qoff) {
    int e = blockIdx.x * blockDim.x + threadIdx.x;
    if (e < TK * HALF) {
        int t = e / HALF, i = e % HALF;
        float bs = (2.0f * i + 0.4f * HD) / (1.4f * HD);
        float invf = powf(10000.0f, -(float)i / HALF);
        float power = ((float)t - 128.0f) / 320.0f;
        float z = powf(bs, -power);
        float th = (float)t * invf;
        g_rotc[e] = cosf(th) * z;
        g_rots[e] = sinf(th) * z;
    } else if (e < TK * HALF + HALF) {
        int i = e - TK * HALF;
        int off = qoff[0];
        int total = off + 1;
        int minp = -((total + 1) >> 1);
        float bs = (2.0f * i + 0.4f * HD) / (1.4f * HD);
        float invf = powf(10000.0f, -(float)i / HALF);
        float pq = (float)(minp + total - 1) / 320.0f;
        float z = powf(bs, pq);
        float th = (float)(total - 1) * invf;
        g_qc[i] = cosf(th) * z;
        g_qs[i] = sinf(th) * z;
    }
}

__global__ void k_embed(const int* __restrict__ toks, const float* __restrict__ table) {
    int h = blockIdx.x, d = threadIdx.x;
    g_tgt[h * D + d] = table[(long)toks[h] * D + d];
}

__global__ void k_rowstats(const float* __restrict__ cached) {
    int row = blockIdx.x * 8 + (threadIdx.x >> 5);
    if (row >= NL * NHYP * TCACHE) return;
    int lane = threadIdx.x & 31;
    const float* p = cached + (long)row * D;
    float s = 0.f, s2 = 0.f;
    for (int j = lane; j < D; j += 32) {
        float v = p[j];
        s += v;
        s2 += v * v;
    }
#pragma unroll
    for (int o = 16; o; o >>= 1) {
        s += __shfl_xor_sync(0xffffffffu, s, o);
        s2 += __shfl_xor_sync(0xffffffffu, s2, o);
    }
    if (lane == 0) {
        float mu = s * (1.0f / D);
        float var = s2 * (1.0f / D) - mu * mu;
        g_mu[row] = mu;
        g_rs[row] = rsqrtf(var + 1e-5f);
    }
}

// ---------------- K-projection GEMM piece (one z), R12 pipelined inner ----------------
// grid (128, 5), 256 threads. z<5 -> self layer z; z>=5 -> cross layer z-5.
// SELF MODE NEVER WRITES ROW 255 — that row is owned by k_qk on the main stream.
#define GBM 128
#define GBN 64
#define GBK 32
__global__ void __launch_bounds__(256) k_gemm_one(
    int z,
    const float* __restrict__ cached, const float* __restrict__ memory,
    const float* __restrict__ ln_w, const float* __restrict__ ln_b,
    const float* __restrict__ sa_w, const float* __restrict__ sa_b,
    const float* __restrict__ ca_w, const float* __restrict__ ca_b) {
    __shared__ uint32_t As[GBM][GBK + 4];
    __shared__ uint32_t Bs[GBK][GBN + 8];
    __shared__ float sw[D], sb[D];
    bool selfmode = (z < 5);
    int l = selfmode ? z : z - 5;
    const float* Araw = selfmode ? cached + (long)l * NHYP * TCACHE * D : memory;
    const float* B = (selfmode ? sa_w : ca_w) + (long)l * 4 * D * D + D * D;
    const float* bias = (selfmode ? sa_b : ca_b) + l * 4 * D + D;
    float* out = (selfmode ? g_kself : g_kcross) + (long)l * NHYP * TK * D;
    int loff = l * NHYP * TCACHE;
    int tid = threadIdx.x;
    if (selfmode) {
        const float* lw = ln_w + l * 3 * D;
        const float* lb = ln_b + l * 3 * D;
        for (int i = tid; i < D; i += 256) {
            sw[i] = lw[i];
            sb[i] = lb[i];
        }
    }
    __syncthreads();
    int m0 = blockIdx.x * GBM, n0 = blockIdx.y * GBN;
    int warp = tid >> 5, lane = tid & 31;
    int wm = warp >> 1, wn = warp & 1;
    int g = lane >> 2, c = lane & 3;
    float acc[2][4][4];
#pragma unroll
    for (int a = 0; a < 2; a++)
#pragma unroll
        for (int bb = 0; bb < 4; bb++)
#pragma unroll
            for (int cc = 0; cc < 4; cc++) acc[a][bb][cc] = 0.f;

    int arow[4], ac4[4], at[4], ar[4];
#pragma unroll
    for (int i = 0; i < 4; i++) {
        int idx = tid + 256 * i;
        arow[i] = idx >> 3;
        ac4[i] = (idx & 7) * 4;
        int m = m0 + arow[i];
        at[i] = m & 255;
        ar[i] = (m >> 8) * TCACHE + at[i];
    }
    int bk_[2], bn4[2];
#pragma unroll
    for (int i = 0; i < 2; i++) {
        int idx = tid + 256 * i;
        bk_[i] = idx >> 4;
        bn4[i] = (idx & 15) * 4;
    }

    float4 va[4], vb[2];
    float muR[4], rsR[4];

#pragma unroll
    for (int i = 0; i < 4; i++) {
        va[i] = make_float4(0.f, 0.f, 0.f, 0.f);
        muR[i] = 0.f;
        rsR[i] = 0.f;
        if (selfmode) {
            if (at[i] < TCACHE) {
                va[i] = *(const float4*)&Araw[(long)ar[i] * D + ac4[i]];
                muR[i] = g_mu[loff + ar[i]];
                rsR[i] = g_rs[loff + ar[i]];
            }
        } else {
            va[i] = *(const float4*)&Araw[(long)(m0 + arow[i]) * D + ac4[i]];
        }
    }
#pragma unroll
    for (int i = 0; i < 2; i++)
        vb[i] = *(const float4*)&B[(long)bk_[i] * D + n0 + bn4[i]];

    for (int k0 = 0; k0 < D; k0 += GBK) {
#pragma unroll
        for (int i = 0; i < 4; i++) {
            float4 v = va[i];
            if (selfmode && at[i] < TCACHE) {
                float m_ = muR[i], rr = rsR[i];
                v.x = (v.x - m_) * rr * sw[k0 + ac4[i] + 0] + sb[k0 + ac4[i] + 0];
                v.y = (v.y - m_) * rr * sw[k0 + ac4[i] + 1] + sb[k0 + ac4[i] + 1];
                v.z = (v.z - m_) * rr * sw[k0 + ac4[i] + 2] + sb[k0 + ac4[i] + 2];
                v.w = (v.w - m_) * rr * sw[k0 + ac4[i] + 3] + sb[k0 + ac4[i] + 3];
            }
            As[arow[i]][ac4[i] + 0] = f2tf(v.x);
            As[arow[i]][ac4[i] + 1] = f2tf(v.y);
            As[arow[i]][ac4[i] + 2] = f2tf(v.z);
            As[arow[i]][ac4[i] + 3] = f2tf(v.w);
        }
#pragma unroll
        for (int i = 0; i < 2; i++) {
            Bs[bk_[i]][bn4[i] + 0] = f2tf(vb[i].x);
            Bs[bk_[i]][bn4[i] + 1] = f2tf(vb[i].y);
            Bs[bk_[i]][bn4[i] + 2] = f2tf(vb[i].z);
            Bs[bk_[i]][bn4[i] + 3] = f2tf(vb[i].w);
        }
        __syncthreads();
        int kn = k0 + GBK;
        if (kn < D) {
#pragma unroll
            for (int i = 0; i < 4; i++) {
                if (selfmode) {
                    if (at[i] < TCACHE)
                        va[i] = *(const float4*)&Araw[(long)ar[i] * D + kn + ac4[i]];
                } else {
                    va[i] = *(const float4*)&Araw[(long)(m0 + arow[i]) * D + kn + ac4[i]];
                }
            }
#pragma unroll
            for (int i = 0; i < 2; i++)
                vb[i] = *(const float4*)&B[(long)(kn + bk_[i]) * D + n0 + bn4[i]];
        }
#pragma unroll
        for (int ks = 0; ks < 4; ks++) {
            uint32_t afr[2][4], bfr[4][2];
#pragma unroll
            for (int mi = 0; mi < 2; mi++) {
                int r = wm * 32 + mi * 16;
                afr[mi][0] = As[r + g][ks * 8 + c];
                afr[mi][1] = As[r + g + 8][ks * 8 + c];
                afr[mi][2] = As[r + g][ks * 8 + c + 4];
                afr[mi][3] = As[r + g + 8][ks * 8 + c + 4];
            }
#pragma unroll
            for (int ni = 0; ni < 4; ni++) {
                int nn = wn * 32 + ni * 8;
                bfr[ni][0] = Bs[ks * 8 + c][nn + g];
                bfr[ni][1] = Bs[ks * 8 + c + 4][nn + g];
            }
#pragma unroll
            for (int mi = 0; mi < 2; mi++)
#pragma unroll
                for (int ni = 0; ni < 4; ni++) mma_tf32(acc[mi][ni], afr[mi], bfr[ni]);
        }
        __syncthreads();
    }
    // ---- epilogue: bias + rotation.  Self-mode skips row 255 (owned by k_qk). ----
#pragma unroll
    for (int mi = 0; mi < 2; mi++) {
        int r0 = m0 + wm * 32 + mi * 16 + g;
        int r1 = r0 + 8;
        int t0 = r0 & 255, t1 = r1 & 255;
        bool st0 = !(selfmode && t0 == TCACHE);
        bool st1 = !(selfmode && t1 == TCACHE);
#pragma unroll
        for (int ni = 0; ni < 4; ni++) {
            int nn = n0 + wn * 32 + ni * 8 + 2 * c;
            int p = (nn % HD) >> 1;
            float be = bias[nn], bo = bias[nn + 1];
            if (st0) {
                float cc = g_rotc[t0 * HALF + p], ss = g_rots[t0 * HALF + p];
                float e = acc[mi][ni][0] + be, o = acc[mi][ni][1] + bo;
                *(float2*)&out[(long)r0 * D + nn] =
                    make_float2(e * cc - o * ss, o * cc + e * ss);
            }
            if (st1) {
                float cc = g_rotc[t1 * HALF + p], ss = g_rots[t1 * HALF + p];
                float e = acc[mi][ni][2] + be, o = acc[mi][ni][3] + bo;
                *(float2*)&out[(long)r1 * D + nn] =
                    make_float2(e * cc - o * ss, o * cc + e * ss);
            }
        }
    }
}

// ---------------- fused LN + q-proj (+ k255-proj for self) ----------------
// grid (64, 2, selfmode?2:1), block (160, 4)
__global__ void k_qk(int selfmode, int l,
                     const float* __restrict__ lnw, const float* __restrict__ lnb,
                     const float* __restrict__ Wq, const float* __restrict__ bq,
                     const float* __restrict__ Wk, const float* __restrict__ bk) {
    __shared__ float xs[D];
    __shared__ float part[4][160];
    __shared__ float qv[160];
    __shared__ float red[20];
    __shared__ float mv[2];
    int h = blockIdx.x, tx = threadIdx.x, ty = threadIdx.y;
    int ft = ty * 160 + tx;
    int lane = ft & 31, warp = ft >> 5;
    float v = (ft < D) ? g_tgt[h * D + ft] : 0.f;
    float s = v;
#pragma unroll
    for (int o = 16; o; o >>= 1) s += __shfl_xor_sync(0xffffffffu, s, o);
    if (lane == 0) red[warp] = s;
    __syncthreads();
    if (ft == 0) {
        float a = 0.f;
        for (int i = 0; i < 20; i++) a += red[i];
        mv[0] = a * (1.0f / D);
    }
    __syncthreads();
    float mu = mv[0];
    float dv = v - mu;
    float q2 = (ft < D) ? dv * dv : 0.f;
#pragma unroll
    for (int o = 16; o; o >>= 1) q2 += __shfl_xor_sync(0xffffffffu, q2, o);
    if (lane == 0) red[warp] = q2;
    __syncthreads();
    if (ft == 0) {
        float a = 0.f;
        for (int i = 0; i < 20; i++) a += red[i];
        mv[1] = rsqrtf(a * (1.0f / D) + 1e-5f);
    }
    __syncthreads();
    if (ft < D) xs[ft] = dv * mv[1] * lnw[ft] + lnb[ft];
    __syncthreads();
    if (selfmode && blockIdx.y == 0 && blockIdx.z == 0 && ft < D)
        g_nt0[h * D + ft] = xs[ft];
    const float* W = (blockIdx.z == 0) ? Wq : Wk;
    const float* bias = (blockIdx.z == 0) ? bq : bk;
    int n = blockIdx.y * 160 + tx;
    float acc = 0.f;
    int k0 = ty * 80;
#pragma unroll 8
    for (int k = k0; k < k0 + 80; k++) acc += xs[k] * W[k * D + n];
    part[ty][tx] = acc;
    __syncthreads();
    if (ty == 0) {
        float t = part[0][tx] + part[1][tx] + part[2][tx] + part[3][tx] + bias[n];
        qv[tx] = (blockIdx.z == 0) ? t * 0.11180339887498949f : t;
    }
    __syncthreads();
    if (ty == 0) {
        int p = (n % HD) >> 1;
        float cc, ss;
        if (blockIdx.z == 0) {
            cc = g_qc[p];
            ss = g_qs[p];
        } else {
            cc = g_rotc[TCACHE * HALF + p];
            ss = g_rots[TCACHE * HALF + p];
        }
        float e = qv[tx & ~1], o = qv[tx | 1];
        float r = (n & 1) ? (o * cc + e * ss) : (e * cc - o * ss);
        if (blockIdx.z == 0)
            g_q[h * D + n] = r;
        else
            g_kself[(long)l * NHYP * TK * D + ((long)h * TK + TCACHE) * D + n] = r;
    }
}

// ---------------- fused attention + out-projection ----------------
// grid 64, block (320, 2)
__global__ void k_attn_out(const float* __restrict__ X, int selfmode, int loff, int l,
                           const float* __restrict__ lnw, const float* __restrict__ lnb,
                           const unsigned char* __restrict__ mask,
                           const float* __restrict__ Wv, const float* __restrict__ bv,
                           const float* __restrict__ Wo, const float* __restrict__ bo) {
    __shared__ float qs[D];
    __shared__ float p[NH][TK];
    __shared__ float ys[NH][D];
    __shared__ float py[2][NH][D];
    __shared__ float part[2][D];
    __shared__ float red[2][8];
    __shared__ float val[2];
    __shared__ float redc[4][4];
    __shared__ float corr[NH];
    int h = blockIdx.x, tx = threadIdx.x, ty = threadIdx.y;
    int ft = ty * 320 + tx;
    int warp = ft >> 5, lane = ft & 31;
    const float* K = (selfmode ? g_kself : g_kcross) + (long)l * NHYP * TK * D +
                     (long)h * TK * D;
    if (ty == 0) qs[tx] = g_q[h * D + tx];
    __syncthreads();
#pragma unroll
    for (int i = 0; i < 13; i++) {
        int t = warp * 13 + i;
        if (t < TK) {
            const float* kr = K + (long)t * D;
            float sc[NH];
#pragma unroll
            for (int hh = 0; hh < NH; hh++) {
                int d0 = hh * HD + lane;
                float s = qs[d0] * kr[d0] + qs[d0 + 32] * kr[d0 + 32];
                if (lane < 16) s += qs[d0 + 64] * kr[d0 + 64];
                sc[hh] = s;
            }
#pragma unroll
            for (int hh = 0; hh < NH; hh++)
#pragma unroll
                for (int o = 16; o; o >>= 1)
                    sc[hh] += __shfl_xor_sync(0xffffffffu, sc[hh], o);
            if (lane == 0) {
                bool msk = (mask != nullptr) && (mask[h * TK + t] != 0);
#pragma unroll
                for (int hh = 0; hh < NH; hh++) p[hh][t] = msk ? -1e30f : sc[hh];
            }
        }
    }
    __syncthreads();
    for (int pass = 0; pass < 2; pass++) {
        bool act = (ft < 512);
        int grp = (ft >> 8) & 1;
        int hh = pass * 2 + grp;
        int t = ft & 255;
        float lv = act ? p[hh][t] : -1e30f;
        float m = lv;
#pragma unroll
        for (int o = 16; o; o >>= 1) m = fmaxf(m, __shfl_xor_sync(0xffffffffu, m, o));
        if (act && lane == 0) red[grp][(ft >> 5) & 7] = m;
        __syncthreads();
        if (act && (ft & 255) == 0) {
            float mm = red[grp][0];
            for (int j = 1; j < 8; j++) mm = fmaxf(mm, red[grp][j]);
            val[grp] = mm;
        }
        __syncthreads();
        float ex = act ? expf(lv - val[grp]) : 0.f;
        float ssum = ex;
#pragma unroll
        for (int o = 16; o; o >>= 1) ssum += __shfl_xor_sync(0xffffffffu, ssum, o);
        if (act && lane == 0) red[grp][(ft >> 5) & 7] = ssum;
        __syncthreads();
        if (act && (ft & 255) == 0) {
            float ss = 0.f;
            for (int j = 0; j < 8; j++) ss += red[grp][j];
            val[grp] = ss;
        }
        __syncthreads();
        if (act) p[hh][t] = ex / val[grp];
        __syncthreads();
    }
    if (selfmode) {
        float c1 = 0.f;
        if (ft < 512) {
            int hh = ft >> 7, t0 = ft & 127;
            int r = loff + h * TCACHE;
            float p0 = p[hh][t0] * g_rs[r + t0];
            c1 = p0 * g_mu[r + t0];
            p[hh][t0] = p0;
            if (t0 < 127) {
                float p1 = p[hh][t0 + 128] * g_rs[r + t0 + 128];
                c1 += p1 * g_mu[r + t0 + 128];
                p[hh][t0 + 128] = p1;
            }
        }
#pragma unroll
        for (int o = 16; o; o >>= 1) c1 += __shfl_xor_sync(0xffffffffu, c1, o);
        if (ft < 512 && lane == 0) redc[ft >> 7][(ft >> 5) & 3] = c1;
        __syncthreads();
        if (ft < 512 && (ft & 127) == 0) {
            int hh = ft >> 7;
            corr[hh] = redc[hh][0] + redc[hh][1] + redc[hh][2] + redc[hh][3];
        }
        __syncthreads();
    }
    {
        float a0 = 0.f, a1 = 0.f, a2 = 0.f, a3 = 0.f;
        int stride = selfmode ? TCACHE : TK;
        int tlo = ty * 128;
        int thi = ty ? stride : 128;
        const float* base = X + (long)h * stride * D + tx;
        for (int t = tlo; t < thi; t++) {
            float xv = base[(long)t * D];
            a0 += p[0][t] * xv;
            a1 += p[1][t] * xv;
            a2 += p[2][t] * xv;
            a3 += p[3][t] * xv;
        }
        py[ty][0][tx] = a0;
        py[ty][1][tx] = a1;
        py[ty][2][tx] = a2;
        py[ty][3][tx] = a3;
    }
    __syncthreads();
    if (ty == 0) {
        if (selfmode) {
            float w = lnw[tx], b = lnb[tx], nv = g_nt0[h * D + tx];
#pragma unroll
            for (int hh = 0; hh < NH; hh++) {
                float a = py[0][hh][tx] + py[1][hh][tx];
                float pf = p[hh][TCACHE];
                ys[hh][tx] = (a - corr[hh]) * w + (1.f - pf) * b + pf * nv;
            }
        } else {
#pragma unroll
            for (int hh = 0; hh < NH; hh++) ys[hh][tx] = py[0][hh][tx] + py[1][hh][tx];
        }
    }
    __syncthreads();
    {
        int hh = tx / HD;
        const float* yb = ys[hh];
        float z = 0.f;
        int d0 = ty * 160;
#pragma unroll 8
        for (int d2 = d0; d2 < d0 + 160; d2++) z += yb[d2] * Wv[d2 * D + tx];
        part[ty][tx] = z;
    }
    __syncthreads();
    if (ty == 0) qs[tx] = part[0][tx] + part[1][tx] + bv[tx];
    __syncthreads();
    {
        float o = 0.f;
        int m0 = ty * 160;
#pragma unroll 8
        for (int m = m0; m < m0 + 160; m++) o += qs[m] * Wo[m * D + tx];
        part[ty][tx] = o;
    }
    __syncthreads();
    if (ty == 0) g_tgt[h * D + tx] += part[0][tx] + part[1][tx] + bo[tx];
}

// ---------------- FF1 with fused LN ----------------
__global__ void __launch_bounds__(256) k_ff1(const float* __restrict__ lnw,
                                             const float* __restrict__ lnb,
                                             const float* __restrict__ W1,
                                             const float* __restrict__ b1) {
    __shared__ float Aln[16][D + 1];
    __shared__ float Wsm[32][68];
    int h0 = blockIdx.x * 16, n0 = blockIdx.y * 64;
    int tid = threadIdx.x;
    int w = tid >> 5, lane = tid & 31;
#pragma unroll
    for (int rr = 0; rr < 2; rr++) {
        int row = w * 2 + rr;
        const float* src = g_tgt + (h0 + row) * D;
        float s = 0.f, s2 = 0.f;
        for (int j = lane; j < D; j += 32) {
            float x = src[j];
            s += x;
            s2 += x * x;
        }
#pragma unroll
        for (int o = 16; o; o >>= 1) {
            s += __shfl_xor_sync(0xffffffffu, s, o);
            s2 += __shfl_xor_sync(0xffffffffu, s2, o);
        }
        float mu = s * (1.0f / D);
        float rsd = rsqrtf(s2 * (1.0f / D) - mu * mu + 1e-5f);
        for (int j = lane; j < D; j += 32)
            Aln[row][j] = (src[j] - mu) * rsd * lnw[j] + lnb[j];
    }
    __syncthreads();
    int tx = tid & 15, ty = tid >> 4;
    float acc0 = 0.f, acc1 = 0.f, acc2 = 0.f, acc3 = 0.f;
    for (int k0 = 0; k0 < D; k0 += 32) {
#pragma unroll
        for (int i = 0; i < 2; i++) {
            int id2 = tid + 256 * i;
            int rr = id2 >> 4, c4 = (id2 & 15) * 4;
            float4 v = *(const float4*)&W1[(long)(k0 + rr) * FF + n0 + c4];
            Wsm[rr][c4 + 0] = v.x;
            Wsm[rr][c4 + 1] = v.y;
            Wsm[rr][c4 + 2] = v.z;
            Wsm[rr][c4 + 3] = v.w;
        }
        __syncthreads();
#pragma unroll
        for (int k = 0; k < 32; k++) {
            float a = Aln[ty][k0 + k];
            acc0 += a * Wsm[k][tx * 4 + 0];
            acc1 += a * Wsm[k][tx * 4 + 1];
            acc2 += a * Wsm[k][tx * 4 + 2];
            acc3 += a * Wsm[k][tx * 4 + 3];
        }
        __syncthreads();
    }
    int row = h0 + ty, n = n0 + tx * 4;
    float* op = &g_ff[(long)row * FF + n];
    op[0] = fmaxf(acc0 + b1[n + 0], 0.f);
    op[1] = fmaxf(acc1 + b1[n + 1], 0.f);
    op[2] = fmaxf(acc2 + b1[n + 2], 0.f);
    op[3] = fmaxf(acc3 + b1[n + 3], 0.f);
}

// ---------------- FF2 with K-split + atomicAdd ----------------
__global__ void __launch_bounds__(256) k_ff2(const float* __restrict__ W2,
                                             const float* __restrict__ b2) {
    __shared__ float Asm[16][33];
    __shared__ float Wsm[32][68];
    int h0 = blockIdx.x * 16, n0 = blockIdx.y * 64, kz = blockIdx.z;
    int tid = threadIdx.x, tx = tid & 15, ty = tid >> 4;
    float acc0 = 0.f, acc1 = 0.f, acc2 = 0.f, acc3 = 0.f;
    for (int k0 = kz * 512; k0 < kz * 512 + 512; k0 += 32) {
        {
            int r = tid >> 5, kk = tid & 31;
            Asm[r][kk] = g_ff[(long)(h0 + r) * FF + k0 + kk];
            Asm[r + 8][kk] = g_ff[(long)(h0 + r + 8) * FF + k0 + kk];
#pragma unroll
            for (int i = 0; i < 2; i++) {
                int id2 = tid + 256 * i;
                int rr = id2 >> 4, c4 = (id2 & 15) * 4;
                float4 v = *(const float4*)&W2[(long)(k0 + rr) * D + n0 + c4];
                Wsm[rr][c4 + 0] = v.x;
                Wsm[rr][c4 + 1] = v.y;
                Wsm[rr][c4 + 2] = v.z;
                Wsm[rr][c4 + 3] = v.w;
            }
        }
        __syncthreads();
#pragma unroll
        for (int k = 0; k < 32; k++) {
            float a = Asm[ty][k];
            acc0 += a * Wsm[k][tx * 4 + 0];
            acc1 += a * Wsm[k][tx * 4 + 1];
            acc2 += a * Wsm[k][tx * 4 + 2];
            acc3 += a * Wsm[k][tx * 4 + 3];
        }
        __syncthreads();
    }
    int row = h0 + ty, n = n0 + tx * 4;
    if (kz == 0) {
        acc0 += b2[n + 0];
        acc1 += b2[n + 1];
        acc2 += b2[n + 2];
        acc3 += b2[n + 3];
    }
    atomicAdd(&g_tgt[row * D + n + 0], acc0);
    atomicAdd(&g_tgt[row * D + n + 1], acc1);
    atomicAdd(&g_tgt[row * D + n + 2], acc2);
    atomicAdd(&g_tgt[row * D + n + 3], acc3);
}

__global__ void k_copy_out(float* __restrict__ out) {
    out[blockIdx.x * D + threadIdx.x] = g_tgt[blockIdx.x * D + threadIdx.x];
}

// ---------------- launch: fork/join stream overlap ----------------
extern "C" void kernel_launch(void* const* d_in, const int* in_sizes, int n_in,
                              void* d_out, int out_size) {
    const int* toks = (const int*)d_in[0];
    const float* cached = (const float*)d_in[1];
    const float* memory = (const float*)d_in[2];
    const unsigned char* mmask = (const unsigned char*)d_in[3];
    const int* qoff = (const int*)d_in[4];
    const float* table = (const float*)d_in[5];
    const float* ln_w = (const float*)d_in[6];
    const float* ln_b = (const float*)d_in[7];
    const float* sa_w = (const float*)d_in[8];
    const float* sa_b = (const float*)d_in[9];
    const float* ca_w = (const float*)d_in[10];
    const float* ca_b = (const float*)d_in[11];
    const float* ff1w = (const float*)d_in[12];
    const float* ff1b = (const float*)d_in[13];
    const float* ff2w = (const float*)d_in[14];
    const float* ff2b = (const float*)d_in[15];

    // host-side objects; bounded leak (kernel_launch runs only a handful of times)
    cudaStream_t s1;
    cudaStreamCreateWithFlags(&s1, cudaStreamNonBlocking);
    cudaEvent_t evFork, evG[10];
    cudaEventCreateWithFlags(&evFork, cudaEventDisableTiming);
    for (int i = 0; i < 10; i++)
        cudaEventCreateWithFlags(&evG[i], cudaEventDisableTiming);

    // ---- prologue on main (capturing) stream ----
    k_tables<<<41, 256>>>(qoff);
    k_embed<<<NHYP, D>>>(toks, table);
    k_rowstats<<<(NL * NHYP * TCACHE + 7) / 8, 256>>>(cached);

    // ---- fork: K-projection GEMM pieces on side stream, consumption order ----
    cudaEventRecord(evFork, 0);
    cudaStreamWaitEvent(s1, evFork, 0);
    const int zorder[10] = {0, 5, 1, 6, 2, 7, 3, 8, 4, 9};
    for (int i = 0; i < 10; i++) {
        k_gemm_one<<<dim3(128, 5), 256, 0, s1>>>(zorder[i], cached, memory, ln_w,
                                                 ln_b, sa_w, sa_b, ca_w, ca_b);
        cudaEventRecord(evG[zorder[i]], s1);
    }

    for (int l = 0; l < NL; l++) {
        const float* lw = ln_w + l * 3 * D;
        const float* lb = ln_b + l * 3 * D;
        const float* sw = sa_w + (long)l * 4 * D * D;
        const float* sb = sa_b + l * 4 * D;
        const float* cw = ca_w + (long)l * 4 * D * D;
        const float* cb = ca_b + l * 4 * D;
        const float* cache_l = cached + (long)l * NHYP * TCACHE * D;
        int loff = l * NHYP * TCACHE;

        // ---- self-attention ----
        k_qk<<<dim3(NHYP, 2, 2), dim3(160, 4)>>>(1, l, lw, lb, sw, sb,
                                                 sw + D * D, sb + D);
        cudaStreamWaitEvent(0, evG[l], 0);      // join: need g_kself[l] rows 0..254
        k_attn_out<<<NHYP, dim3(320, 2)>>>(cache_l, 1, loff, l, lw, lb, nullptr,
                                           sw + 2 * D * D, sb + 2 * D,
                                           sw + 3 * D * D, sb + 3 * D);
        // ---- cross-attention ----
        k_qk<<<dim3(NHYP, 2, 1), dim3(160, 4)>>>(0, l, lw + D, lb + D, cw, cb,
                                                 nullptr, nullptr);
        cudaStreamWaitEvent(0, evG[5 + l], 0);  // join: need g_kcross[l]
        k_attn_out<<<NHYP, dim3(320, 2)>>>(memory, 0, 0, l, nullptr, nullptr, mmask,
                                           cw + 2 * D * D, cb + 2 * D,
                                           cw + 3 * D * D, cb + 3 * D);
        // ---- feed-forward ----
        k_ff1<<<dim3(4, FF / 64), 256>>>(lw + 2 * D, lb + 2 * D,
                                         ff1w + (long)l * D * FF, ff1b + l * FF);
        k_ff2<<<dim3(4, 5, 4), 256>>>(ff2w + (long)l * FF * D, ff2b + l * D);
    }
    k_copy_out<<<NHYP, D>>>((float*)d_out);
}